// round 14
// baseline (speedup 1.0000x reference)
#include <cuda_runtime.h>

// Hierarchical 2-additive Choquet integral, B=16, DEPTH=6.
// Launch 1: fused levels 1+2 (32768 blocks; block = 32 L1 nodes -> 2 L2 nodes),
//           with L2-prefetch of the epilogue (upper-level) theta rows.
// Launch 2: fused levels 3+4 (128 blocks) + last-block computes levels 5+6.

#define NTH 136

__device__ float g_buf0[1 << 20];
__device__ float g_buf1[1 << 16];
__device__ unsigned int g_sync = 0;

// Closed-form triu-index inversion (matches np.triu_indices(16, k=1) order).
__device__ __forceinline__ void fill_lut(unsigned int* s_lut4)
{
    const int t = threadIdx.x;
    if (t < NTH) {
        int i, j;
        if (t < 16) { i = t; j = t; }           // singleton -> min(x_k,x_k)=x_k
        else {
            const int rem = t - 16;
            int ii = (int)((31.0f - sqrtf(961.0f - 8.0f * (float)rem)) * 0.5f);
            int S = 15 * ii - (ii * (ii - 1)) / 2;
            if (rem < S) { --ii; S = 15 * ii - (ii * (ii - 1)) / 2; }
            else { const int S2 = S + (15 - ii); if (rem >= S2) { ++ii; S = S2; } }
            i = ii; j = ii + 1 + (rem - S);
        }
        ((unsigned char*)s_lut4)[t] = (unsigned char)(i | (j << 4));
    }
}

__device__ __forceinline__ void accum4(float xv, float4 tv, unsigned int pk,
                                       float& num, float& den)
{
#pragma unroll
    for (int e = 0; e < 4; ++e) {
        const float tvk = (e == 0) ? tv.x : (e == 1) ? tv.y : (e == 2) ? tv.z : tv.w;
        const int b = (pk >> (8 * e)) & 0xff;
        const float a = __shfl_sync(0xffffffffu, xv, b & 15, 16);
        const float c = __shfl_sync(0xffffffffu, xv, b >> 4, 16);
        const float ex = __expf(tvk);
        den += ex;
        num = fmaf(ex, fminf(a, c), num);
    }
}

__device__ __forceinline__ void accum_tail(float xv, float sc, unsigned int lb,
                                           float& num, float& den)
{
    const float a = __shfl_sync(0xffffffffu, xv, lb & 15, 16);
    const float c = __shfl_sync(0xffffffffu, xv, lb >> 4, 16);
    const float ex = __expf(sc);            // sc = -1e30f on idle lanes -> ex = 0
    den += ex;
    num = fmaf(ex, fminf(a, c), num);
}

// Merged butterfly: on return lanes hl<8 hold (v=num_total, w=den_total).
__device__ __forceinline__ void reduce_merged(float num, float den, int hl,
                                              float& v, float& w)
{
    num += __shfl_xor_sync(0xffffffffu, num, 8);
    den += __shfl_xor_sync(0xffffffffu, den, 8);
    v = (hl < 8) ? num : den;
    v += __shfl_xor_sync(0xffffffffu, v, 4);
    v += __shfl_xor_sync(0xffffffffu, v, 2);
    v += __shfl_xor_sync(0xffffffffu, v, 1);
    w = __shfl_xor_sync(0xffffffffu, v, 8);
}

// One node per 16-lane half. Returns num/den on lanes hl<8.
__device__ __forceinline__ float choquet_half(float xv, const float* __restrict__ th,
                                              const unsigned int* s_lut4)
{
    const int hl = threadIdx.x & 15;
    float num = 0.f, den = 0.f;
    accum4(xv, __ldg(&((const float4*)th)[hl]),      s_lut4[hl],      num, den);
    accum4(xv, __ldg(&((const float4*)th)[hl + 16]), s_lut4[hl + 16], num, den);
    const bool act = hl < 8;
    accum_tail(xv, act ? __ldg(&th[128 + hl]) : -1e30f,
               act ? ((const unsigned char*)s_lut4)[128 + hl] : 0u, num, den);
    float v, w;
    reduce_merged(num, den, hl, v, w);
    return __fdividef(v, w);
}

// L2 prefetch of one 128B line.
__device__ __forceinline__ void prefetch_l2(const void* p)
{
    asm volatile("prefetch.global.L2 [%0];" :: "l"(p));
}

// ---------------------------------------------------------------------------
// Fused lower+upper body. Block = 32 lower nodes -> 2 upper nodes (written to out).
// ---------------------------------------------------------------------------
__device__ __forceinline__ void fused2_body(const float* __restrict__ vals,
                                            const float* __restrict__ thL,
                                            const float* __restrict__ thU,
                                            float* __restrict__ out,
                                            const unsigned int* s_lut4,
                                            float* s1)
{
    const int lane = threadIdx.x & 31;
    const int warp = threadIdx.x >> 5;       // 0..7
    const int hl   = lane & 15;
    const int hi   = lane >> 4;
    const bool act = hl < 8;

    // Warp 0: prefetch the epilogue's 2 upper theta rows (1088 B = 9 lines) to L2,
    // so the post-barrier LDGs hit L2 instead of DRAM. Zero register cost.
    if (warp == 0 && lane < 9) {
        const char* pU = (const char*)(thU + (size_t)(blockIdx.x * 2) * NTH);
        prefetch_l2(pU + lane * 128);
    }

    // ---- lower level: 4 nodes per warp ----
    const int n0   = blockIdx.x * 32 + warp * 4;   // global lower-node base
    const int nl   = warp * 4;                     // block-local base

    const float xv0 = __ldg(&vals[n0 * 16 + lane]);
    const float xv1 = __ldg(&vals[n0 * 16 + 32 + lane]);

    const float* rowA = thL + (size_t)(n0 + hi) * NTH;
    const float* rowB = thL + (size_t)(n0 + 2 + hi) * NTH;
    const float4 t00 = __ldg(&((const float4*)rowA)[hl]);
    const float4 t01 = __ldg(&((const float4*)rowA)[hl + 16]);
    const float4 t10 = __ldg(&((const float4*)rowB)[hl]);
    const float4 t11 = __ldg(&((const float4*)rowB)[hl + 16]);
    const float s0 = act ? __ldg(&rowA[128 + hl]) : -1e30f;
    const float s1v = act ? __ldg(&rowB[128 + hl]) : -1e30f;

    const unsigned int pkA = s_lut4[hl];
    const unsigned int pkB = s_lut4[hl + 16];
    const unsigned int lbT = act ? ((const unsigned char*)s_lut4)[128 + hl] : 0u;

    float num0 = 0.f, den0 = 0.f;
    accum4(xv0, t00, pkA, num0, den0);
    accum4(xv0, t01, pkB, num0, den0);
    accum_tail(xv0, s0, lbT, num0, den0);

    float num1 = 0.f, den1 = 0.f;
    accum4(xv1, t10, pkA, num1, den1);
    accum4(xv1, t11, pkB, num1, den1);
    accum_tail(xv1, s1v, lbT, num1, den1);

    float v0, w0, v1, w1;
    reduce_merged(num0, den0, hl, v0, w0);
    reduce_merged(num1, den1, hl, v1, w1);

    if (hl == 0) {
        s1[nl + hi]     = __fdividef(v0, w0);
        s1[nl + 2 + hi] = __fdividef(v1, w1);
    }
    __syncthreads();

    // ---- upper level: warp 0 computes the block's 2 upper nodes ----
    if (warp == 0) {
        const int nodeU = blockIdx.x * 2 + hi;
        const float xv = s1[hi * 16 + hl];
        const float r  = choquet_half(xv, thU + (size_t)nodeU * NTH, s_lut4);
        if (hl == 0) out[nodeU] = r;
    }
}

// Launch 1: levels 1+2.
__global__ void __launch_bounds__(256)
choquet_fused12_kernel(const float* __restrict__ vals,
                       const float* __restrict__ thL,
                       const float* __restrict__ thU,
                       float* __restrict__ out)
{
    __shared__ unsigned int s_lut4[34];
    __shared__ float s1[32];
    fill_lut(s_lut4);
    __syncthreads();
    fused2_body(vals, thL, thU, out, s_lut4, s1);
}

// Launch 2: levels 3+4 (128 blocks), last block also does levels 5+6.
__global__ void __launch_bounds__(256)
choquet_fused3456_kernel(const float* __restrict__ vals,   // 65536 level-2 outputs
                         const float* __restrict__ th3,
                         const float* __restrict__ th4,
                         float* __restrict__ v4,           // 256 level-4 outputs
                         const float* __restrict__ th5,
                         const float* __restrict__ th6,
                         float* __restrict__ out)
{
    __shared__ unsigned int s_lut4[34];
    __shared__ float s1[32];
    __shared__ float s5[16];
    __shared__ unsigned int s_last;
    fill_lut(s_lut4);
    __syncthreads();

    fused2_body(vals, th3, th4, v4, s_lut4, s1);

    // last-block detection (threadFenceReduction pattern)
    __threadfence();                       // writers (tid 0,16) push v4 stores
    __syncthreads();
    if (threadIdx.x == 0) {
        const unsigned int old = atomicAdd(&g_sync, 1u);
        s_last = (old == gridDim.x - 1) ? 1u : 0u;
    }
    __syncthreads();
    if (s_last == 0u) return;

    // ---- last block: levels 5 + 6 ----
    __threadfence();                       // acquire: v4 writes from other blocks
    if (threadIdx.x == 0) g_sync = 0;      // reset for next graph replay

    const int warp = threadIdx.x >> 5;     // 0..7
    const int lane = threadIdx.x & 31;
    const int node = warp * 2 + (lane >> 4);

    // level 5: 16 nodes across 8 warps (plain loads — coherent via L2)
    const float xv = v4[warp * 32 + lane];
    const float r  = choquet_half(xv, th5 + (size_t)node * NTH, s_lut4);
    if ((lane & 15) == 0) s5[node] = r;
    __syncthreads();

    // level 6: root on warp 0 (both halves mirror it)
    if (warp == 0) {
        const float x2 = s5[lane & 15];
        const float root = choquet_half(x2, th6, s_lut4);
        if (lane == 0) out[0] = root;
    }
}

extern "C" void kernel_launch(void* const* d_in, const int* in_sizes, int n_in,
                              void* d_out, int out_size)
{
    (void)in_sizes; (void)n_in; (void)out_size;

    const float* x   = (const float*)d_in[0];
    const float* th1 = (const float*)d_in[1];
    const float* th2 = (const float*)d_in[2];
    const float* th3 = (const float*)d_in[3];
    const float* th4 = (const float*)d_in[4];
    const float* th5 = (const float*)d_in[5];
    const float* th6 = (const float*)d_in[6];
    float* out = (float*)d_out;

    float *b0, *b1;
    cudaGetSymbolAddress((void**)&b0, g_buf0);
    cudaGetSymbolAddress((void**)&b1, g_buf1);

    // levels 1+2: 1,048,576 -> 65,536  (32768 blocks)
    choquet_fused12_kernel<<<32768, 256>>>(x, th1, th2, b1);
    // levels 3+4+5+6: 65,536 -> 1  (128 blocks, last block finishes)
    choquet_fused3456_kernel<<<128, 256>>>(b1, th3, th4, b0, th5, th6, out);
}

// round 17
// speedup vs baseline: 1.0573x; 1.0573x over previous
#include <cuda_runtime.h>

// Hierarchical 2-additive Choquet integral, B=16, DEPTH=6.
// Fused pairs of levels: block = 32 lower nodes (8 warps x 4) -> 2 upper nodes.
// Upper-level theta rows staged into 16B-ALIGNED smem at kernel start (latency
// hidden under the lower-level compute), so the warp-0 epilogue has no exposed
// DRAM chain. 3 launches: fused(x,th1,th2) -> fused(b1,th3,th4) -> l56.

#define NTH 136

__device__ float g_buf0[1 << 20];
__device__ float g_buf1[1 << 16];

// Closed-form triu-index inversion (matches np.triu_indices(16, k=1) order).
__device__ __forceinline__ void fill_lut(unsigned int* s_lut4)
{
    const int t = threadIdx.x;
    if (t < NTH) {
        int i, j;
        if (t < 16) { i = t; j = t; }           // singleton -> min(x_k,x_k)=x_k
        else {
            const int rem = t - 16;
            int ii = (int)((31.0f - sqrtf(961.0f - 8.0f * (float)rem)) * 0.5f);
            int S = 15 * ii - (ii * (ii - 1)) / 2;
            if (rem < S) { --ii; S = 15 * ii - (ii * (ii - 1)) / 2; }
            else { const int S2 = S + (15 - ii); if (rem >= S2) { ++ii; S = S2; } }
            i = ii; j = ii + 1 + (rem - S);
        }
        ((unsigned char*)s_lut4)[t] = (unsigned char)(i | (j << 4));
    }
}

__device__ __forceinline__ void accum4(float xv, float4 tv, unsigned int pk,
                                       float& num, float& den)
{
#pragma unroll
    for (int e = 0; e < 4; ++e) {
        const float tvk = (e == 0) ? tv.x : (e == 1) ? tv.y : (e == 2) ? tv.z : tv.w;
        const int b = (pk >> (8 * e)) & 0xff;
        const float a = __shfl_sync(0xffffffffu, xv, b & 15, 16);
        const float c = __shfl_sync(0xffffffffu, xv, b >> 4, 16);
        const float ex = __expf(tvk);
        den += ex;
        num = fmaf(ex, fminf(a, c), num);
    }
}

__device__ __forceinline__ void accum_tail(float xv, float sc, unsigned int lb,
                                           float& num, float& den)
{
    const float a = __shfl_sync(0xffffffffu, xv, lb & 15, 16);
    const float c = __shfl_sync(0xffffffffu, xv, lb >> 4, 16);
    const float ex = __expf(sc);            // sc = -1e30f on idle lanes -> ex = 0
    den += ex;
    num = fmaf(ex, fminf(a, c), num);
}

// Merged butterfly: on return lanes hl<8 hold (v=num_total, w=den_total).
__device__ __forceinline__ void reduce_merged(float num, float den, int hl,
                                              float& v, float& w)
{
    num += __shfl_xor_sync(0xffffffffu, num, 8);
    den += __shfl_xor_sync(0xffffffffu, den, 8);
    v = (hl < 8) ? num : den;
    v += __shfl_xor_sync(0xffffffffu, v, 4);
    v += __shfl_xor_sync(0xffffffffu, v, 2);
    v += __shfl_xor_sync(0xffffffffu, v, 1);
    w = __shfl_xor_sync(0xffffffffu, v, 8);
}

// One node per 16-lane half, thetas via generic loads (smem or gmem pointer;
// MUST be 16B aligned). Returns num/den on lanes hl<8.
__device__ __forceinline__ float choquet_half(float xv, const float* th,
                                              const unsigned int* s_lut4)
{
    const int hl = threadIdx.x & 15;
    const float4* th4 = (const float4*)th;
    float num = 0.f, den = 0.f;
    accum4(xv, th4[hl],      s_lut4[hl],      num, den);
    accum4(xv, th4[hl + 16], s_lut4[hl + 16], num, den);
    const bool act = hl < 8;
    accum_tail(xv, act ? th[128 + hl] : -1e30f,
               act ? ((const unsigned char*)s_lut4)[128 + hl] : 0u, num, den);
    float v, w;
    reduce_merged(num, den, hl, v, w);
    return __fdividef(v, w);
}

// ---------------------------------------------------------------------------
// Fused lower+upper body. Block = 32 lower nodes -> 2 upper nodes.
// s_thU: 272-float, 16B-aligned smem buffer for the block's 2 upper theta rows.
// ---------------------------------------------------------------------------
__device__ __forceinline__ void fused2_body(const float* __restrict__ vals,
                                            const float* __restrict__ thL,
                                            const float* __restrict__ thU,
                                            float* __restrict__ out,
                                            const unsigned int* s_lut4,
                                            float* s1, float* s_thU)
{
    const int lane = threadIdx.x & 31;
    const int warp = threadIdx.x >> 5;       // 0..7
    const int hl   = lane & 15;
    const int hi   = lane >> 4;
    const bool act = hl < 8;

    // ---- stage upper thetas to smem (68 float4 = 1088 B, one LDG for tid<68) ----
    // Latency overlaps the lower-level compute below; visibility via __syncthreads.
    if (threadIdx.x < 68) {
        ((float4*)s_thU)[threadIdx.x] =
            __ldg(&((const float4*)(thU + (size_t)(blockIdx.x * 2) * NTH))[threadIdx.x]);
    }

    // ---- lower level: 4 nodes per warp ----
    const int n0   = blockIdx.x * 32 + warp * 4;   // global lower-node base
    const int nl   = warp * 4;                     // block-local base

    const float xv0 = __ldg(&vals[n0 * 16 + lane]);
    const float xv1 = __ldg(&vals[n0 * 16 + 32 + lane]);

    const float* rowA = thL + (size_t)(n0 + hi) * NTH;
    const float* rowB = thL + (size_t)(n0 + 2 + hi) * NTH;
    const float4 t00 = __ldg(&((const float4*)rowA)[hl]);
    const float4 t01 = __ldg(&((const float4*)rowA)[hl + 16]);
    const float4 t10 = __ldg(&((const float4*)rowB)[hl]);
    const float4 t11 = __ldg(&((const float4*)rowB)[hl + 16]);
    const float s0 = act ? __ldg(&rowA[128 + hl]) : -1e30f;
    const float s1v = act ? __ldg(&rowB[128 + hl]) : -1e30f;

    const unsigned int pkA = s_lut4[hl];
    const unsigned int pkB = s_lut4[hl + 16];
    const unsigned int lbT = act ? ((const unsigned char*)s_lut4)[128 + hl] : 0u;

    float num0 = 0.f, den0 = 0.f;
    accum4(xv0, t00, pkA, num0, den0);
    accum4(xv0, t01, pkB, num0, den0);
    accum_tail(xv0, s0, lbT, num0, den0);

    float num1 = 0.f, den1 = 0.f;
    accum4(xv1, t10, pkA, num1, den1);
    accum4(xv1, t11, pkB, num1, den1);
    accum_tail(xv1, s1v, lbT, num1, den1);

    float v0, w0, v1, w1;
    reduce_merged(num0, den0, hl, v0, w0);
    reduce_merged(num1, den1, hl, v1, w1);

    if (hl == 0) {
        s1[nl + hi]     = __fdividef(v0, w0);
        s1[nl + 2 + hi] = __fdividef(v1, w1);
    }
    __syncthreads();

    // ---- upper level: warp 0, thetas from smem (no exposed DRAM latency) ----
    if (warp == 0) {
        const int nodeU = blockIdx.x * 2 + hi;
        const float xv = s1[hi * 16 + hl];
        const float r  = choquet_half(xv, s_thU + hi * NTH, s_lut4);  // hi*544B: 16B-aligned
        if (hl == 0) out[nodeU] = r;
    }
}

__global__ void __launch_bounds__(256)
choquet_fused2_kernel(const float* __restrict__ vals,
                      const float* __restrict__ thL,
                      const float* __restrict__ thU,
                      float* __restrict__ out)
{
    __shared__ unsigned int s_lut4[34];
    __shared__ float s1[32];
    __shared__ __align__(16) float s_thU[2 * NTH];
    fill_lut(s_lut4);
    __syncthreads();
    fused2_body(vals, thL, thU, out, s_lut4, s1, s_thU);
}

// ---------------------------------------------------------------------------
// Levels 5 (16 nodes) + 6 (root): one small block.
// ---------------------------------------------------------------------------
__global__ void __launch_bounds__(256)
choquet_l56_kernel(const float* __restrict__ v4,    // 256 level-4 outputs
                   const float* __restrict__ th5,   // 16 x 136
                   const float* __restrict__ th6,   // 1 x 136
                   float* __restrict__ out)
{
    __shared__ unsigned int s_lut4[34];
    __shared__ float s5[16];
    fill_lut(s_lut4);
    __syncthreads();

    const int warp = threadIdx.x >> 5;   // 0..7
    const int lane = threadIdx.x & 31;
    const int node = warp * 2 + (lane >> 4);

    const float xv = __ldg(&v4[warp * 32 + lane]);
    const float r  = choquet_half(xv, th5 + (size_t)node * NTH, s_lut4);
    if ((lane & 15) == 0) s5[node] = r;
    __syncthreads();

    if (warp == 0) {
        const float x2 = s5[lane & 15];
        const float root = choquet_half(x2, th6, s_lut4);
        if (lane == 0) out[0] = root;
    }
}

extern "C" void kernel_launch(void* const* d_in, const int* in_sizes, int n_in,
                              void* d_out, int out_size)
{
    (void)in_sizes; (void)n_in; (void)out_size;

    const float* x   = (const float*)d_in[0];
    const float* th1 = (const float*)d_in[1];
    const float* th2 = (const float*)d_in[2];
    const float* th3 = (const float*)d_in[3];
    const float* th4 = (const float*)d_in[4];
    const float* th5 = (const float*)d_in[5];
    const float* th6 = (const float*)d_in[6];
    float* out = (float*)d_out;

    float *b0, *b1;
    cudaGetSymbolAddress((void**)&b0, g_buf0);
    cudaGetSymbolAddress((void**)&b1, g_buf1);

    // levels 1+2: 1,048,576 -> 65,536  (32768 blocks)
    choquet_fused2_kernel<<<32768, 256>>>(x, th1, th2, b1);
    // levels 3+4: 4096 lower -> 256 upper  (128 blocks)
    choquet_fused2_kernel<<<128, 256>>>(b1, th3, th4, b0);
    // levels 5+6
    choquet_l56_kernel<<<1, 256>>>(b0, th5, th6, out);
}